// round 1
// baseline (speedup 1.0000x reference)
#include <cuda_runtime.h>
#include <math.h>

#define NB 65536
#define ND 768
#define NS 64
#define NT 17
#define T_MAX 2.0f
#define DT (T_MAX / (float)NT)
#define EPSV 1e-8f

// ---------------- device scratch (static allocations only) ----------------
__device__ float g_projT[NS * NB];   // proj transposed: [s][b], 16 MB
__device__ float g_dirinv[NS];       // 1/||dirs[:,s]||
__device__ float g_colsum[ND];
__device__ float g_colsq[ND];
__device__ float g_psum[NS];
__device__ float g_psq[NS];
__device__ float g_pmean[NS];
__device__ float g_pinvstd[NS];
__device__ float g_ecfr[NT * NS];
__device__ float g_ecfi[NT * NS];

// ---------------- kernel 0: zero accumulators (graph is replayed!) --------
__global__ void k_init() {
    int i = blockIdx.x * blockDim.x + threadIdx.x;
    if (i < ND)      { g_colsum[i] = 0.f; g_colsq[i] = 0.f; }
    if (i < NS)      { g_psum[i]   = 0.f; g_psq[i]   = 0.f; }
    if (i < NT * NS) { g_ecfr[i]   = 0.f; g_ecfi[i]  = 0.f; }
}

// ---------------- kernel 1: direction column inverse norms ----------------
__global__ void k_dirnorm(const float* __restrict__ dirs) {
    int s = threadIdx.x;            // 64 threads
    float acc = 0.f;
    for (int d = 0; d < ND; d++) {
        float v = dirs[d * NS + s]; // coalesced across threads
        acc += v * v;
    }
    g_dirinv[s] = 1.0f / sqrtf(acc);
}

// ---------------- kernel 2: per-dim sums/sumsq of z (for var_floor) -------
// 256 blocks x 256 threads, each block handles 256 rows; thread t owns
// columns {t, t+256, t+512} -> 6 register accumulators, zero smem.
__global__ __launch_bounds__(256) void k_colstats(const float* __restrict__ z) {
    int r0 = blockIdx.x * 256;
    int t = threadIdx.x;
    float s0 = 0.f, s1 = 0.f, s2 = 0.f, q0 = 0.f, q1 = 0.f, q2 = 0.f;
    for (int r = 0; r < 256; r++) {
        const float* row = z + (size_t)(r0 + r) * ND;
        float a = row[t], b = row[t + 256], c = row[t + 512];
        s0 += a; q0 += a * a;
        s1 += b; q1 += b * b;
        s2 += c; q2 += c * c;
    }
    atomicAdd(&g_colsum[t],       s0); atomicAdd(&g_colsq[t],       q0);
    atomicAdd(&g_colsum[t + 256], s1); atomicAdd(&g_colsq[t + 256], q1);
    atomicAdd(&g_colsum[t + 512], s2); atomicAdd(&g_colsq[t + 512], q2);
}

// ---------------- kernel 3: GEMM projT[s][b] = z[b,:] . dirs_norm[:,s] ----
// Tile: 64 b-rows x 64 s-cols per block, K chunk 16, 256 threads,
// 4x4 micro-tile per thread. Output written transposed for coalesced ECF.
__global__ __launch_bounds__(256) void k_gemm(const float* __restrict__ z,
                                              const float* __restrict__ dirs) {
    __shared__ __align__(16) float As[16][68];  // [k][b], padded
    __shared__ __align__(16) float Bs[16][64];  // [k][s]

    int tid = threadIdx.x;
    int b0 = blockIdx.x * 64;

    int arow = tid >> 2, aq = tid & 3;      // As loader mapping
    int bk = tid >> 4, bq = tid & 15;       // Bs loader mapping
    float inv0 = g_dirinv[bq * 4 + 0];
    float inv1 = g_dirinv[bq * 4 + 1];
    float inv2 = g_dirinv[bq * 4 + 2];
    float inv3 = g_dirinv[bq * 4 + 3];

    int br = (tid >> 4) * 4;                // compute mapping: b offset
    int sc = (tid & 15) * 4;                // s offset

    float acc[4][4];
    #pragma unroll
    for (int i = 0; i < 4; i++)
        #pragma unroll
        for (int j = 0; j < 4; j++) acc[i][j] = 0.f;

    for (int kc = 0; kc < ND; kc += 16) {
        float4 av = *(const float4*)(z + (size_t)(b0 + arow) * ND + kc + aq * 4);
        float4 bv = *(const float4*)(dirs + (size_t)(kc + bk) * NS + bq * 4);
        bv.x *= inv0; bv.y *= inv1; bv.z *= inv2; bv.w *= inv3;

        __syncthreads();   // protect previous iteration's reads
        As[aq * 4 + 0][arow] = av.x;
        As[aq * 4 + 1][arow] = av.y;
        As[aq * 4 + 2][arow] = av.z;
        As[aq * 4 + 3][arow] = av.w;
        *(float4*)&Bs[bk][bq * 4] = bv;
        __syncthreads();

        #pragma unroll
        for (int k = 0; k < 16; k++) {
            float4 a  = *(const float4*)&As[k][br];
            float4 bb = *(const float4*)&Bs[k][sc];
            acc[0][0] += a.x * bb.x; acc[0][1] += a.x * bb.y;
            acc[0][2] += a.x * bb.z; acc[0][3] += a.x * bb.w;
            acc[1][0] += a.y * bb.x; acc[1][1] += a.y * bb.y;
            acc[1][2] += a.y * bb.z; acc[1][3] += a.y * bb.w;
            acc[2][0] += a.z * bb.x; acc[2][1] += a.z * bb.y;
            acc[2][2] += a.z * bb.z; acc[2][3] += a.z * bb.w;
            acc[3][0] += a.w * bb.x; acc[3][1] += a.w * bb.y;
            acc[3][2] += a.w * bb.z; acc[3][3] += a.w * bb.w;
        }
    }

    // store transposed: projT[(sc+j)*NB + b0+br .. +3] as float4
    #pragma unroll
    for (int j = 0; j < 4; j++) {
        float4 v = make_float4(acc[0][j], acc[1][j], acc[2][j], acc[3][j]);
        *(float4*)(g_projT + (size_t)(sc + j) * NB + b0 + br) = v;
    }
}

// ---------------- kernel 4: per-s sums of proj ----------------------------
__global__ __launch_bounds__(256) void k_pstats() {
    int s = blockIdx.y;
    size_t base = (size_t)s * NB + blockIdx.x * 2048;
    float sum = 0.f, sq = 0.f;
    #pragma unroll
    for (int i = 0; i < 8; i++) {
        float v = g_projT[base + threadIdx.x + i * 256];
        sum += v; sq += v * v;
    }
    unsigned m = 0xffffffffu;
    #pragma unroll
    for (int off = 16; off; off >>= 1) {
        sum += __shfl_down_sync(m, sum, off);
        sq  += __shfl_down_sync(m, sq,  off);
    }
    if ((threadIdx.x & 31) == 0) {
        atomicAdd(&g_psum[s], sum);
        atomicAdd(&g_psq[s],  sq);
    }
}

// ---------------- kernel 5: finalize proj mean/invstd ---------------------
__global__ void k_pfinal() {
    int s = threadIdx.x;  // 64
    float mean = g_psum[s] / (float)NB;
    float var = (g_psq[s] - (float)NB * mean * mean) / (float)(NB - 1);
    g_pmean[s] = mean;
    g_pinvstd[s] = 1.0f / (sqrtf(fmaxf(var, 0.f)) + EPSV);
}

// ---------------- kernel 6: ECF sums via rotation recurrence --------------
// One sincos per element, then 16 complex rotations for the 17 t points.
__global__ __launch_bounds__(256) void k_ecf() {
    int s = blockIdx.y;
    float mean = g_pmean[s], invstd = g_pinvstd[s];
    size_t base = (size_t)s * NB + blockIdx.x * 4096;

    float cr[NT], ci[NT];
    #pragma unroll
    for (int j = 0; j < NT; j++) { cr[j] = 0.f; ci[j] = 0.f; }

    #pragma unroll 4
    for (int i = 0; i < 16; i++) {
        float p = (g_projT[base + threadIdx.x + i * 256] - mean) * invstd;
        float c1, s1;
        __sincosf(DT * p, &s1, &c1);
        float ck = c1, sk = s1;
        #pragma unroll
        for (int j = 0; j < NT; j++) {
            cr[j] += ck; ci[j] += sk;
            float cn = ck * c1 - sk * s1;
            sk = sk * c1 + ck * s1;
            ck = cn;
        }
    }

    unsigned m = 0xffffffffu;
    #pragma unroll
    for (int j = 0; j < NT; j++) {
        float r = cr[j], im = ci[j];
        #pragma unroll
        for (int off = 16; off; off >>= 1) {
            r  += __shfl_down_sync(m, r,  off);
            im += __shfl_down_sync(m, im, off);
        }
        if ((threadIdx.x & 31) == 0) {
            atomicAdd(&g_ecfr[j * NS + s], r);
            atomicAdd(&g_ecfi[j * NS + s], im);
        }
    }
}

// ---------------- kernel 7: final scalar loss ------------------------------
__global__ __launch_bounds__(256) void k_final(float* __restrict__ out) {
    __shared__ float red[256];
    int t = threadIdx.x;
    float acc = 0.f;

    // var_floor = mean(relu(1 - std(z, ddof=1))) over 768 dims
    for (int d = t; d < ND; d += 256) {
        float mean = g_colsum[d] / (float)NB;
        float var = (g_colsq[d] - (float)NB * mean * mean) / (float)(NB - 1);
        float stdv = sqrtf(fmaxf(var, 0.f));
        acc += fmaxf(1.0f - stdv, 0.f) * (1.0f / (float)ND);
    }

    // quadrature: sum_j w_j * mean_s(er^2 + ei^2 - 2 er tcf + tcf^2)
    for (int idx = t; idx < NT * NS; idx += 256) {
        int j = idx / NS;
        float tj = DT * (float)(j + 1);
        float er = g_ecfr[idx] / (float)NB;
        float ei = g_ecfi[idx] / (float)NB;
        float tcf = expf(-0.5f * tj * tj);
        float term = er * er + ei * ei - 2.0f * er * tcf + tcf * tcf;
        float w = DT * ((j == 0 || j == NT - 1) ? 0.5f : 1.0f);
        acc += w * term * (1.0f / (float)NS);
    }

    red[t] = acc;
    __syncthreads();
    for (int off = 128; off; off >>= 1) {
        if (t < off) red[t] += red[t + off];
        __syncthreads();
    }
    if (t == 0) out[0] = red[0];
}

// ---------------- launch ----------------------------------------------------
extern "C" void kernel_launch(void* const* d_in, const int* in_sizes, int n_in,
                              void* d_out, int out_size) {
    const float* z    = (const float*)d_in[0];   // [65536, 768]
    const float* dirs = (const float*)d_in[1];   // [768, 64]
    float* out = (float*)d_out;

    k_init<<<5, 256>>>();
    k_dirnorm<<<1, 64>>>(dirs);
    k_colstats<<<256, 256>>>(z);
    k_gemm<<<NB / 64, 256>>>(z, dirs);
    k_pstats<<<dim3(32, NS), 256>>>();
    k_pfinal<<<1, NS>>>();
    k_ecf<<<dim3(16, NS), 256>>>();
    k_final<<<1, 256>>>(out);
}

// round 2
// speedup vs baseline: 1.1028x; 1.1028x over previous
#include <cuda_runtime.h>
#include <math.h>

#define NB 65536
#define ND 768
#define NS 64
#define NT 17
#define T_MAX 2.0f
#define DT (T_MAX / (float)NT)
#define EPSV 1e-8f

typedef unsigned long long ull;

// ---------------- device scratch ----------------
__device__ float g_projT[NS * NB];   // proj transposed [s][b]
__device__ float g_dirinv[NS];
__device__ float g_colsum[ND];
__device__ float g_colsq[ND];
__device__ float g_psum[NS];
__device__ float g_psq[NS];
__device__ float g_pmean[NS];
__device__ float g_pinvstd[NS];
__device__ float g_ecfr[NT * NS];
__device__ float g_ecfi[NT * NS];

// packed-f32x2 helpers (ptxas won't auto-fuse FFMA2 from C++)
__device__ __forceinline__ ull dup2(float v) {
    ull r; asm("mov.b64 %0, {%1, %1};" : "=l"(r) : "f"(v)); return r;
}
__device__ __forceinline__ void fma2(ull& d, ull a, ull b) {
    asm("fma.rn.f32x2 %0, %1, %2, %0;" : "+l"(d) : "l"(a), "l"(b));
}
__device__ __forceinline__ float2 unpack2(ull v) {
    float2 f; asm("mov.b64 {%0, %1}, %2;" : "=f"(f.x), "=f"(f.y) : "l"(v)); return f;
}

// ---------------- kernel 0: zero accumulators (graph is replayed) ----------
__global__ void k_init() {
    int i = blockIdx.x * blockDim.x + threadIdx.x;
    if (i < ND)      { g_colsum[i] = 0.f; g_colsq[i] = 0.f; }
    if (i < NS)      { g_psum[i]   = 0.f; g_psq[i]   = 0.f; }
    if (i < NT * NS) { g_ecfr[i]   = 0.f; g_ecfi[i]  = 0.f; }
}

// ---------------- kernel 1: direction column inverse norms ----------------
__global__ void k_dirnorm(const float* __restrict__ dirs) {
    int s = threadIdx.x;            // 64 threads
    float acc = 0.f;
    for (int d = 0; d < ND; d++) {
        float v = dirs[d * NS + s];
        acc += v * v;
    }
    g_dirinv[s] = 1.0f / sqrtf(acc);
}

// ---------------- kernel 2: per-dim sums/sumsq of z (var_floor) ------------
// 512 blocks x 192 threads; thread owns 4 columns (float4), 128 rows/block.
__global__ __launch_bounds__(192) void k_colstats(const float* __restrict__ z) {
    int c = threadIdx.x * 4;
    size_t base = (size_t)blockIdx.x * 128 * ND + c;
    float s0 = 0.f, s1 = 0.f, s2 = 0.f, s3 = 0.f;
    float q0 = 0.f, q1 = 0.f, q2 = 0.f, q3 = 0.f;
    #pragma unroll 4
    for (int r = 0; r < 128; r++) {
        float4 v = *(const float4*)(z + base + (size_t)r * ND);
        s0 += v.x; q0 += v.x * v.x;
        s1 += v.y; q1 += v.y * v.y;
        s2 += v.z; q2 += v.z * v.z;
        s3 += v.w; q3 += v.w * v.w;
    }
    atomicAdd(&g_colsum[c + 0], s0); atomicAdd(&g_colsq[c + 0], q0);
    atomicAdd(&g_colsum[c + 1], s1); atomicAdd(&g_colsq[c + 1], q1);
    atomicAdd(&g_colsum[c + 2], s2); atomicAdd(&g_colsq[c + 2], q2);
    atomicAdd(&g_colsum[c + 3], s3); atomicAdd(&g_colsq[c + 3], q3);
}

// ---------------- kernel 3: GEMM projT = (z @ dirs_norm)^T -----------------
// 64 threads/block, block tile 64 b-rows x 64 s, 8x8 micro-tile, FFMA2.
// Also fuses per-s sum/sumsq of proj (kills the old k_pstats pass).
__global__ __launch_bounds__(64) void k_gemm(const float* __restrict__ z,
                                             const float* __restrict__ dirs) {
    __shared__ __align__(16) float As[16][68];   // [k][brow]
    __shared__ __align__(16) float Bs[16][64];   // [k][s]
    __shared__ float rsum[8][64];
    __shared__ float rsq[8][64];

    const int tid = threadIdx.x;
    const int b0 = blockIdx.x * 64;

    // compute mapping: 8 row-groups x 8 s-groups
    const int tr = tid >> 3;        // rows tr*8 .. tr*8+7
    const int ts = tid & 7;         // cols ts*8 .. ts*8+7

    // A loader: per pass p: row = lrow + 16p, k = lkq*4..+3
    const int lrow = tid >> 2;
    const int lkq  = tid & 3;
    // B loader: per pass q: k = bk + 4q, s = bq*4..+3
    const int bk = tid >> 4;
    const int bq = tid & 15;
    const float inv0 = g_dirinv[bq * 4 + 0];
    const float inv1 = g_dirinv[bq * 4 + 1];
    const float inv2 = g_dirinv[bq * 4 + 2];
    const float inv3 = g_dirinv[bq * 4 + 3];

    ull acc[4][8];
    #pragma unroll
    for (int i = 0; i < 4; i++)
        #pragma unroll
        for (int j = 0; j < 8; j++) acc[i][j] = 0ull;

    float4 pa[4], pb[4];
    // prefetch chunk 0
    #pragma unroll
    for (int p = 0; p < 4; p++)
        pa[p] = *(const float4*)(z + (size_t)(b0 + lrow + 16 * p) * ND + lkq * 4);
    #pragma unroll
    for (int q = 0; q < 4; q++)
        pb[q] = *(const float4*)(dirs + (size_t)(bk + 4 * q) * NS + bq * 4);

    for (int kc = 0; kc < ND; kc += 16) {
        __syncthreads();   // protect previous iteration's smem reads
        #pragma unroll
        for (int p = 0; p < 4; p++) {
            As[lkq * 4 + 0][lrow + 16 * p] = pa[p].x;
            As[lkq * 4 + 1][lrow + 16 * p] = pa[p].y;
            As[lkq * 4 + 2][lrow + 16 * p] = pa[p].z;
            As[lkq * 4 + 3][lrow + 16 * p] = pa[p].w;
        }
        #pragma unroll
        for (int q = 0; q < 4; q++) {
            float4 v = pb[q];
            v.x *= inv0; v.y *= inv1; v.z *= inv2; v.w *= inv3;
            *(float4*)&Bs[bk + 4 * q][bq * 4] = v;
        }
        __syncthreads();

        int kn = kc + 16;
        if (kn < ND) {
            #pragma unroll
            for (int p = 0; p < 4; p++)
                pa[p] = *(const float4*)(z + (size_t)(b0 + lrow + 16 * p) * ND + kn + lkq * 4);
            #pragma unroll
            for (int q = 0; q < 4; q++)
                pb[q] = *(const float4*)(dirs + (size_t)(kn + bk + 4 * q) * NS + bq * 4);
        }

        #pragma unroll
        for (int k = 0; k < 16; k++) {
            ulonglong2 a01 = *(const ulonglong2*)&As[k][tr * 8];
            ulonglong2 a23 = *(const ulonglong2*)&As[k][tr * 8 + 4];
            float4 bx = *(const float4*)&Bs[k][ts * 8];
            float4 by = *(const float4*)&Bs[k][ts * 8 + 4];
            ull av[4] = {a01.x, a01.y, a23.x, a23.y};
            ull bd[8];
            bd[0] = dup2(bx.x); bd[1] = dup2(bx.y);
            bd[2] = dup2(bx.z); bd[3] = dup2(bx.w);
            bd[4] = dup2(by.x); bd[5] = dup2(by.y);
            bd[6] = dup2(by.z); bd[7] = dup2(by.w);
            #pragma unroll
            for (int i = 0; i < 4; i++)
                #pragma unroll
                for (int j = 0; j < 8; j++)
                    fma2(acc[i][j], av[i], bd[j]);
        }
    }

    // epilogue: store projT transposed + per-s partial sums
    #pragma unroll
    for (int j = 0; j < 8; j++) {
        float2 r0 = unpack2(acc[0][j]);
        float2 r1 = unpack2(acc[1][j]);
        float2 r2 = unpack2(acc[2][j]);
        float2 r3 = unpack2(acc[3][j]);
        size_t off = (size_t)(ts * 8 + j) * NB + b0 + tr * 8;
        *(float4*)(g_projT + off)     = make_float4(r0.x, r0.y, r1.x, r1.y);
        *(float4*)(g_projT + off + 4) = make_float4(r2.x, r2.y, r3.x, r3.y);
        float s = r0.x + r0.y + r1.x + r1.y + r2.x + r2.y + r3.x + r3.y;
        float q = r0.x * r0.x + r0.y * r0.y + r1.x * r1.x + r1.y * r1.y
                + r2.x * r2.x + r2.y * r2.y + r3.x * r3.x + r3.y * r3.y;
        rsum[tr][ts * 8 + j] = s;
        rsq[tr][ts * 8 + j]  = q;
    }
    __syncthreads();
    // 64 threads reduce 8 row-groups each
    {
        float s = 0.f, q = 0.f;
        #pragma unroll
        for (int t = 0; t < 8; t++) { s += rsum[t][tid]; q += rsq[t][tid]; }
        atomicAdd(&g_psum[tid], s);
        atomicAdd(&g_psq[tid],  q);
    }
}

// ---------------- kernel 5: finalize proj mean/invstd ----------------------
__global__ void k_pfinal() {
    int s = threadIdx.x;  // 64
    float mean = g_psum[s] / (float)NB;
    float var = (g_psq[s] - (float)NB * mean * mean) / (float)(NB - 1);
    g_pmean[s] = mean;
    g_pinvstd[s] = 1.0f / (sqrtf(fmaxf(var, 0.f)) + EPSV);
}

// ---------------- kernel 6: ECF sums via rotation recurrence ---------------
__global__ __launch_bounds__(256) void k_ecf() {
    int s = blockIdx.y;
    float mean = g_pmean[s], invstd = g_pinvstd[s];
    size_t base = (size_t)s * NB + blockIdx.x * 4096;

    float cr[NT], ci[NT];
    #pragma unroll
    for (int j = 0; j < NT; j++) { cr[j] = 0.f; ci[j] = 0.f; }

    #pragma unroll 4
    for (int i = 0; i < 16; i++) {
        float p = (g_projT[base + threadIdx.x + i * 256] - mean) * invstd;
        float c1, s1;
        __sincosf(DT * p, &s1, &c1);
        float ck = c1, sk = s1;
        #pragma unroll
        for (int j = 0; j < NT; j++) {
            cr[j] += ck; ci[j] += sk;
            float cn = ck * c1 - sk * s1;
            sk = sk * c1 + ck * s1;
            ck = cn;
        }
    }

    unsigned m = 0xffffffffu;
    #pragma unroll
    for (int j = 0; j < NT; j++) {
        float r = cr[j], im = ci[j];
        #pragma unroll
        for (int off = 16; off; off >>= 1) {
            r  += __shfl_down_sync(m, r,  off);
            im += __shfl_down_sync(m, im, off);
        }
        if ((threadIdx.x & 31) == 0) {
            atomicAdd(&g_ecfr[j * NS + s], r);
            atomicAdd(&g_ecfi[j * NS + s], im);
        }
    }
}

// ---------------- kernel 7: final scalar loss -------------------------------
__global__ __launch_bounds__(256) void k_final(float* __restrict__ out) {
    __shared__ float red[256];
    int t = threadIdx.x;
    float acc = 0.f;

    for (int d = t; d < ND; d += 256) {
        float mean = g_colsum[d] / (float)NB;
        float var = (g_colsq[d] - (float)NB * mean * mean) / (float)(NB - 1);
        float stdv = sqrtf(fmaxf(var, 0.f));
        acc += fmaxf(1.0f - stdv, 0.f) * (1.0f / (float)ND);
    }

    for (int idx = t; idx < NT * NS; idx += 256) {
        int j = idx / NS;
        float tj = DT * (float)(j + 1);
        float er = g_ecfr[idx] / (float)NB;
        float ei = g_ecfi[idx] / (float)NB;
        float tcf = expf(-0.5f * tj * tj);
        float term = er * er + ei * ei - 2.0f * er * tcf + tcf * tcf;
        float w = DT * ((j == 0 || j == NT - 1) ? 0.5f : 1.0f);
        acc += w * term * (1.0f / (float)NS);
    }

    red[t] = acc;
    __syncthreads();
    for (int off = 128; off; off >>= 1) {
        if (t < off) red[t] += red[t + off];
        __syncthreads();
    }
    if (t == 0) out[0] = red[0];
}

// ---------------- launch -----------------------------------------------------
extern "C" void kernel_launch(void* const* d_in, const int* in_sizes, int n_in,
                              void* d_out, int out_size) {
    const float* z    = (const float*)d_in[0];   // [65536, 768]
    const float* dirs = (const float*)d_in[1];   // [768, 64]
    float* out = (float*)d_out;

    k_init<<<5, 256>>>();
    k_dirnorm<<<1, 64>>>(dirs);
    k_colstats<<<512, 192>>>(z);
    k_gemm<<<NB / 64, 64>>>(z, dirs);
    k_pfinal<<<1, NS>>>();
    k_ecf<<<dim3(16, NS), 256>>>();
    k_final<<<1, 256>>>(out);
}

// round 4
// speedup vs baseline: 1.5978x; 1.4489x over previous
#include <cuda_runtime.h>
#include <math.h>
#include <stdint.h>

#define NB 65536
#define ND 768
#define NS 64
#define NT 17
#define T_MAX 2.0f
#define DT (T_MAX / (float)NT)
#define EPSV 1e-8f
#define NKK (ND / 8)   // 96 k-steps of 8

typedef unsigned long long ull;

// ---------------- device scratch ----------------
__device__ float  g_projT[NS * NB];         // proj transposed [s][b]
__device__ float4 g_dirsFrag[NKK * 4 * 32]; // A fragments, tf32, frag-ready
__device__ float  g_dirinv[NS];
__device__ float  g_colsum[ND];
__device__ float  g_colsq[ND];
__device__ float  g_psum[NS];
__device__ float  g_psq[NS];
__device__ float  g_pmean[NS];
__device__ float  g_pinvstd[NS];
__device__ float  g_ecfr[NT * NS];
__device__ float  g_ecfi[NT * NS];

// ---------------- ptx helpers ----------------
__device__ __forceinline__ uint32_t f2tf(float f) {
    uint32_t r; asm("cvt.rna.tf32.f32 %0, %1;" : "=r"(r) : "f"(f)); return r;
}
__device__ __forceinline__ void mma8(float* c, const uint32_t* a,
                                     uint32_t b0, uint32_t b1) {
    asm volatile(
        "mma.sync.aligned.m16n8k8.row.col.f32.tf32.tf32.f32 "
        "{%0,%1,%2,%3},{%4,%5,%6,%7},{%8,%9},{%0,%1,%2,%3};"
        : "+f"(c[0]), "+f"(c[1]), "+f"(c[2]), "+f"(c[3])
        : "r"(a[0]), "r"(a[1]), "r"(a[2]), "r"(a[3]), "r"(b0), "r"(b1));
}

// packed f32x2 helpers
__device__ __forceinline__ ull pack2(float lo, float hi) {
    ull r; asm("mov.b64 %0, {%1, %2};" : "=l"(r) : "f"(lo), "f"(hi)); return r;
}
__device__ __forceinline__ void fma2(ull& d, ull a, ull b) {
    asm("fma.rn.f32x2 %0, %1, %2, %0;" : "+l"(d) : "l"(a), "l"(b));
}
__device__ __forceinline__ ull mul2(ull a, ull b) {
    ull r; asm("mul.rn.f32x2 %0, %1, %2;" : "=l"(r) : "l"(a), "l"(b)); return r;
}
__device__ __forceinline__ ull add2(ull a, ull b) {
    ull r; asm("add.rn.f32x2 %0, %1, %2;" : "=l"(r) : "l"(a), "l"(b)); return r;
}
__device__ __forceinline__ float2 unpk(ull v) {
    float2 f; asm("mov.b64 {%0, %1}, %2;" : "=f"(f.x), "=f"(f.y) : "l"(v)); return f;
}

// ---------------- kernel 0: zero accumulators (graph replayed) -------------
__global__ void k_init() {
    int i = blockIdx.x * blockDim.x + threadIdx.x;
    if (i < ND)      { g_colsum[i] = 0.f; g_colsq[i] = 0.f; }
    if (i < NS)      { g_psum[i]   = 0.f; g_psq[i]   = 0.f; }
    if (i < NT * NS) { g_ecfr[i]   = 0.f; g_ecfi[i]  = 0.f; }
}

// ---------------- kernel 1: direction column inverse norms ----------------
__global__ void k_dirnorm(const float* __restrict__ dirs) {
    int s = threadIdx.x;            // 64
    float acc = 0.f;
    for (int d = 0; d < ND; d++) {
        float v = dirs[d * NS + s];
        acc += v * v;
    }
    g_dirinv[s] = 1.0f / sqrtf(acc);
}

// ---------------- kernel 1b: build tf32 A fragments (normalized dirs) -----
// frag idx = kk*128 + mt*32 + lane; lane: g=lane>>2 (m row), t=lane&3 (k col)
// a0=A[s0][k0] a1=A[s0+8][k0] a2=A[s0][k0+4] a3=A[s0+8][k0+4], s=mt*16+g, k=kk*8+t
__global__ void k_prepfrag(const float* __restrict__ dirs) {
    int idx = blockIdx.x * blockDim.x + threadIdx.x;   // 48*256 = 12288
    int kk = idx >> 7, rem = idx & 127;
    int mt = rem >> 5, lane = rem & 31;
    int g = lane >> 2, t = lane & 3;
    int s0 = mt * 16 + g;
    int k0 = kk * 8 + t;
    float i0 = g_dirinv[s0], i1 = g_dirinv[s0 + 8];
    float4 v;
    v.x = __uint_as_float(f2tf(dirs[(size_t)k0 * NS + s0]       * i0));
    v.y = __uint_as_float(f2tf(dirs[(size_t)k0 * NS + s0 + 8]   * i1));
    v.z = __uint_as_float(f2tf(dirs[(size_t)(k0 + 4) * NS + s0]     * i0));
    v.w = __uint_as_float(f2tf(dirs[(size_t)(k0 + 4) * NS + s0 + 8] * i1));
    g_dirsFrag[idx] = v;
}

// ---------------- kernel 2: per-dim sums/sumsq of z (var_floor) ------------
__global__ __launch_bounds__(192) void k_colstats(const float* __restrict__ z) {
    int c = threadIdx.x * 4;
    size_t base = (size_t)blockIdx.x * 128 * ND + c;
    float s0 = 0.f, s1 = 0.f, s2 = 0.f, s3 = 0.f;
    float q0 = 0.f, q1 = 0.f, q2 = 0.f, q3 = 0.f;
    #pragma unroll 4
    for (int r = 0; r < 128; r++) {
        float4 v = *(const float4*)(z + base + (size_t)r * ND);
        s0 += v.x; q0 += v.x * v.x;
        s1 += v.y; q1 += v.y * v.y;
        s2 += v.z; q2 += v.z * v.z;
        s3 += v.w; q3 += v.w * v.w;
    }
    atomicAdd(&g_colsum[c + 0], s0); atomicAdd(&g_colsq[c + 0], q0);
    atomicAdd(&g_colsum[c + 1], s1); atomicAdd(&g_colsq[c + 1], q1);
    atomicAdd(&g_colsum[c + 2], s2); atomicAdd(&g_colsq[c + 2], q2);
    atomicAdd(&g_colsum[c + 3], s3); atomicAdd(&g_colsq[c + 3], q3);
}

// ---------------- kernel 3: HMMA tf32 GEMM, projT = dirsT @ z^T ------------
// Warp computes full M=64 (4 m16 tiles) x 32 batch cols (4 n8 tiles).
// B fragments (z) loaded straight from global: each z element read exactly once.
// No smem staging, no mainloop syncs. Epilogue fuses per-s sum/sumsq.
__global__ __launch_bounds__(256, 2) void k_gemm(const float* __restrict__ z) {
    __shared__ float ssum[64], ssq[64];
    int tid = threadIdx.x;
    int wid = tid >> 5, lane = tid & 31;
    int g = lane >> 2, t = lane & 3;

    if (tid < 64) { ssum[tid] = 0.f; ssq[tid] = 0.f; }
    __syncthreads();

    int nbase = blockIdx.x * 256 + wid * 32;          // warp's batch base
    const float* zb = z + (size_t)(nbase + g) * ND + t;

    float c[4][4][4];
    #pragma unroll
    for (int mt = 0; mt < 4; mt++)
        #pragma unroll
        for (int nt = 0; nt < 4; nt++)
            #pragma unroll
            for (int r = 0; r < 4; r++) c[mt][nt][r] = 0.f;

    for (int kk = 0; kk < NKK; kk++) {
        uint32_t a[4][4];
        #pragma unroll
        for (int mt = 0; mt < 4; mt++) {
            float4 v = g_dirsFrag[kk * 128 + mt * 32 + lane];
            a[mt][0] = __float_as_uint(v.x);
            a[mt][1] = __float_as_uint(v.y);
            a[mt][2] = __float_as_uint(v.z);
            a[mt][3] = __float_as_uint(v.w);
        }
        uint32_t b0[4], b1[4];
        #pragma unroll
        for (int nt = 0; nt < 4; nt++) {
            b0[nt] = f2tf(__ldg(zb + (size_t)nt * 8 * ND + kk * 8));
            b1[nt] = f2tf(__ldg(zb + (size_t)nt * 8 * ND + kk * 8 + 4));
        }
        #pragma unroll
        for (int mt = 0; mt < 4; mt++)
            #pragma unroll
            for (int nt = 0; nt < 4; nt++)
                mma8(c[mt][nt], a[mt], b0[nt], b1[nt]);
    }

    // epilogue: store projT + fused per-s sums
    #pragma unroll
    for (int mt = 0; mt < 4; mt++) {
        float su0 = 0.f, su1 = 0.f, sq0 = 0.f, sq1 = 0.f;
        int s0 = mt * 16 + g;
        #pragma unroll
        for (int nt = 0; nt < 4; nt++) {
            float d0 = c[mt][nt][0], d1 = c[mt][nt][1];
            float d2 = c[mt][nt][2], d3 = c[mt][nt][3];
            int n = nbase + nt * 8 + t * 2;
            *(float2*)(g_projT + (size_t)s0 * NB + n)       = make_float2(d0, d1);
            *(float2*)(g_projT + (size_t)(s0 + 8) * NB + n) = make_float2(d2, d3);
            su0 += d0 + d1; sq0 += d0 * d0 + d1 * d1;
            su1 += d2 + d3; sq1 += d2 * d2 + d3 * d3;
        }
        // reduce across the 4 t-lanes (same s row)
        #pragma unroll
        for (int off = 1; off < 4; off <<= 1) {
            su0 += __shfl_xor_sync(0xffffffffu, su0, off);
            sq0 += __shfl_xor_sync(0xffffffffu, sq0, off);
            su1 += __shfl_xor_sync(0xffffffffu, su1, off);
            sq1 += __shfl_xor_sync(0xffffffffu, sq1, off);
        }
        if (t == 0) {
            atomicAdd(&ssum[s0], su0);     atomicAdd(&ssq[s0], sq0);
            atomicAdd(&ssum[s0 + 8], su1); atomicAdd(&ssq[s0 + 8], sq1);
        }
    }
    __syncthreads();
    if (tid < 64) {
        atomicAdd(&g_psum[tid], ssum[tid]);
        atomicAdd(&g_psq[tid],  ssq[tid]);
    }
}

// ---------------- kernel 5: finalize proj mean/invstd ----------------------
__global__ void k_pfinal() {
    int s = threadIdx.x;  // 64
    float mean = g_psum[s] / (float)NB;
    float var = (g_psq[s] - (float)NB * mean * mean) / (float)(NB - 1);
    g_pmean[s] = mean;
    g_pinvstd[s] = 1.0f / (sqrtf(fmaxf(var, 0.f)) + EPSV);
}

// ---------------- kernel 6: ECF via packed f32x2 rotation ------------------
__global__ __launch_bounds__(256) void k_ecf() {
    int s = blockIdx.y;
    float mean = g_pmean[s], invstd = g_pinvstd[s];
    size_t basep = (size_t)s * NB + blockIdx.x * 4096;
    const float2* src = (const float2*)(g_projT + basep);

    ull CR[NT], CI[NT];
    #pragma unroll
    for (int j = 0; j < NT; j++) { CR[j] = 0ull; CI[j] = 0ull; }

    #pragma unroll 2
    for (int i = 0; i < 8; i++) {
        float2 pv = src[threadIdx.x + i * 256];
        float p0 = (pv.x - mean) * invstd;
        float p1 = (pv.y - mean) * invstd;
        float c0, s0, c1v, s1v;
        __sincosf(DT * p0, &s0, &c0);
        __sincosf(DT * p1, &s1v, &c1v);
        ull cP  = pack2(c0, c1v);
        ull sP  = pack2(s0, s1v);
        ull nsP = pack2(-s0, -s1v);
        ull ck = cP, sk = sP;
        #pragma unroll
        for (int j = 0; j < NT; j++) {
            CR[j] = add2(CR[j], ck);
            CI[j] = add2(CI[j], sk);
            ull cn = mul2(ck, cP); fma2(cn, sk, nsP);  // ck*c - sk*s
            ull sn = mul2(sk, cP); fma2(sn, ck, sP);   // sk*c + ck*s
            ck = cn; sk = sn;
        }
    }

    unsigned msk = 0xffffffffu;
    #pragma unroll
    for (int j = 0; j < NT; j++) {
        float2 r2 = unpk(CR[j]);
        float2 i2 = unpk(CI[j]);
        float r = r2.x + r2.y, im = i2.x + i2.y;
        #pragma unroll
        for (int off = 16; off; off >>= 1) {
            r  += __shfl_down_sync(msk, r,  off);
            im += __shfl_down_sync(msk, im, off);
        }
        if ((threadIdx.x & 31) == 0) {
            atomicAdd(&g_ecfr[j * NS + s], r);
            atomicAdd(&g_ecfi[j * NS + s], im);
        }
    }
}

// ---------------- kernel 7: final scalar loss -------------------------------
__global__ __launch_bounds__(256) void k_final(float* __restrict__ out) {
    __shared__ float red[256];
    int t = threadIdx.x;
    float acc = 0.f;

    for (int d = t; d < ND; d += 256) {
        float mean = g_colsum[d] / (float)NB;
        float var = (g_colsq[d] - (float)NB * mean * mean) / (float)(NB - 1);
        float stdv = sqrtf(fmaxf(var, 0.f));
        acc += fmaxf(1.0f - stdv, 0.f) * (1.0f / (float)ND);
    }

    for (int idx = t; idx < NT * NS; idx += 256) {
        int j = idx / NS;
        float tj = DT * (float)(j + 1);
        float er = g_ecfr[idx] / (float)NB;
        float ei = g_ecfi[idx] / (float)NB;
        float tcf = expf(-0.5f * tj * tj);
        float term = er * er + ei * ei - 2.0f * er * tcf + tcf * tcf;
        float w = DT * ((j == 0 || j == NT - 1) ? 0.5f : 1.0f);
        acc += w * term * (1.0f / (float)NS);
    }

    red[t] = acc;
    __syncthreads();
    for (int off = 128; off; off >>= 1) {
        if (t < off) red[t] += red[t + off];
        __syncthreads();
    }
    if (t == 0) out[0] = red[0];
}

// ---------------- launch -----------------------------------------------------
extern "C" void kernel_launch(void* const* d_in, const int* in_sizes, int n_in,
                              void* d_out, int out_size) {
    const float* z    = (const float*)d_in[0];   // [65536, 768]
    const float* dirs = (const float*)d_in[1];   // [768, 64]
    float* out = (float*)d_out;

    k_init<<<5, 256>>>();
    k_dirnorm<<<1, 64>>>(dirs);
    k_prepfrag<<<48, 256>>>(dirs);
    k_colstats<<<512, 192>>>(z);
    k_gemm<<<NB / 256, 256>>>(z);
    k_pfinal<<<1, NS>>>();
    k_ecf<<<dim3(16, NS), 256>>>();
    k_final<<<1, 256>>>(out);
}